// round 3
// baseline (speedup 1.0000x reference)
#include <cuda_runtime.h>
#include <math.h>
#include <float.h>

#define BB 64
#define QQ 900
#define TT 128
#define C1 14   // NUM_CLASSES+1

// Scratch (static device globals; no allocation)
__device__ float g_cost[(size_t)BB*TT*QQ];   // cost[b][t][q]
__device__ float g_lse[BB*QQ];
__device__ int   g_pred[BB*TT];              // matched query index per (b,t)
__device__ float g_partial[BB];

// ---------------------------------------------------------------------------
// Kernel 1: cost matrix + logsumexp
// ---------------------------------------------------------------------------
__global__ void __launch_bounds__(256) cost_kernel(
    const float* __restrict__ pc, const float* __restrict__ pb,
    const int* __restrict__ tl, const float* __restrict__ tb)
{
    int b = blockIdx.y;
    int tid = threadIdx.x;
    int q = blockIdx.x * 256 + tid;

    __shared__ int   slab[TT];
    __shared__ float stb[TT * 4];
    __shared__ float sprob[256 * 15];   // stride 15 -> conflict-free dynamic index

    for (int t = tid; t < TT; t += 256) {
        slab[t] = tl[b * TT + t];
        const float* tb4 = tb + ((size_t)b * TT + t) * 4;
        stb[t * 4 + 0] = tb4[0];
        stb[t * 4 + 1] = tb4[1];
        stb[t * 4 + 2] = tb4[2];
        stb[t * 4 + 3] = tb4[3];
    }

    float px = 0.f, py = 0.f, pw = 0.f, ph = 0.f;
    if (q < QQ) {
        const float* lg = pc + ((size_t)b * QQ + q) * C1;
        float l[C1];
        float m = -FLT_MAX;
        #pragma unroll
        for (int c = 0; c < C1; c++) { l[c] = lg[c]; m = fmaxf(m, l[c]); }
        float s = 0.f;
        #pragma unroll
        for (int c = 0; c < C1; c++) {
            float e = expf(l[c] - m);
            sprob[tid * 15 + c] = e;
            s += e;
        }
        float inv = -1.0f / s;   // store NEGATIVE prob (class cost is -prob)
        #pragma unroll
        for (int c = 0; c < C1; c++) sprob[tid * 15 + c] *= inv;
        g_lse[b * QQ + q] = m + logf(s);

        const float* pb4 = pb + ((size_t)b * QQ + q) * 4;
        px = pb4[0]; py = pb4[1]; pw = pb4[2]; ph = pb4[3];
    }
    __syncthreads();
    if (q >= QQ) return;

    float* out = g_cost + (size_t)b * TT * QQ + q;
    #pragma unroll 4
    for (int t = 0; t < TT; t++) {
        float tx = stb[t * 4 + 0], ty = stb[t * 4 + 1];
        float tw = stb[t * 4 + 2], th = stb[t * 4 + 3];
        float l1 = fabsf(px - tx) + fabsf(py - ty) + fabsf(pw - tw) + fabsf(ph - th);
        float cc = sprob[tid * 15 + slab[t]];
        out[(size_t)t * QQ] = cc + l1;
    }
}

// ---------------------------------------------------------------------------
// Kernel 2: exact Hungarian (Jonker-Volgenant) with DEFERRED dual updates.
// One block per batch. spc[] holds ABSOLUTE Dijkstra distances; u/v are only
// touched once per augmenting path. Algebraically identical to the e-maxx
// reference (same selections in exact arithmetic).
// ---------------------------------------------------------------------------
__global__ void __launch_bounds__(256) hungarian_kernel()
{
    int b = blockIdx.x;
    const float* cost = g_cost + (size_t)b * TT * QQ;

    __shared__ double v[QQ + 1];
    __shared__ double spc[QQ + 1];      // absolute shortest-path costs
    __shared__ double u[TT + 1];
    __shared__ short  p[QQ + 1];        // p[j] = row assigned to col j (1-based)
    __shared__ short  way[QQ + 1];      // predecessor column in path tree
    __shared__ unsigned char used[QQ + 1];
    __shared__ double s_minval;         // cumulative delta (abs distance of current node)
    __shared__ double s_ui0;
    __shared__ int    s_j1;             // column just added to the tree
    __shared__ int    s_i0;             // current row
    __shared__ int    s_done;
    __shared__ double red_v[8];
    __shared__ int    red_j[8];

    int tid = threadIdx.x;
    int lane = tid & 31, wid = tid >> 5;

    for (int j = tid; j <= QQ; j += 256) { v[j] = 0.0; p[j] = 0; }
    for (int i = tid; i <= TT; i += 256) u[i] = 0.0;
    __syncthreads();

    for (int i = 1; i <= TT; i++) {
        // per-augment init
        for (int j = tid; j <= QQ; j += 256) { spc[j] = DBL_MAX; used[j] = 0; }
        if (tid == 0) {
            p[0] = (short)i;
            spc[0] = 0.0;
            s_minval = 0.0;
            s_ui0 = u[i];
            s_i0 = i;
            s_j1 = 0;      // "column 0" is the virtual root
            s_done = 0;
            used[0] = 1;
        }
        __syncthreads();

        while (1) {
            int    j1prev = s_j1;
            double minVal = s_minval;
            double ui0    = s_ui0;
            int    i0     = s_i0;
            const float* crow = cost + (size_t)(i0 - 1) * QQ;

            // scan free columns: relax via current row, track block argmin of spc
            double bv = DBL_MAX;
            int    bj = 0x7fffffff;
            for (int j = tid + 1; j <= QQ; j += 256) {
                if (!used[j] && j != j1prev) {
                    double r = minVal + (double)crow[j - 1] - ui0 - v[j];
                    double m = spc[j];
                    if (r < m) { m = r; spc[j] = r; way[j] = (short)j1prev; }
                    if (m < bv) { bv = m; bj = j; }
                }
            }
            #pragma unroll
            for (int o = 16; o; o >>= 1) {
                double ov = __shfl_down_sync(0xffffffffu, bv, o);
                int    oj = __shfl_down_sync(0xffffffffu, bj, o);
                if (ov < bv || (ov == bv && oj < bj)) { bv = ov; bj = oj; }
            }
            if (lane == 0) { red_v[wid] = bv; red_j[wid] = bj; }
            __syncthreads();

            if (tid == 0) {
                bv = red_v[0]; bj = red_j[0];
                #pragma unroll
                for (int k = 1; k < 8; k++) {
                    double ov = red_v[k]; int oj = red_j[k];
                    if (ov < bv || (ov == bv && oj < bj)) { bv = ov; bj = oj; }
                }
                used[j1prev] = 1;          // commit previous column
                int r = p[bj];
                s_minval = bv;
                s_j1 = bj;
                if (r == 0) s_done = 1;    // free column -> sink found
                else { s_i0 = r; s_ui0 = u[r]; }
            }
            __syncthreads();
            if (s_done) break;
        }

        double minF = s_minval;
        int sink = s_j1;

        // one-shot dual update over used columns (p unmodified yet; distinct rows)
        for (int j = tid; j <= QQ; j += 256) {
            if (used[j]) {
                double d = minF - spc[j];
                u[p[j]] += d;
                v[j]    -= d;
            }
        }
        __syncthreads();

        // augment along alternating path
        if (tid == 0) {
            int j0 = sink;
            while (j0) {
                int jn = way[j0];
                p[j0] = p[jn];
                j0 = jn;
            }
        }
        __syncthreads();
    }

    for (int j = tid + 1; j <= QQ; j += 256) {
        int r = p[j];
        if (r > 0) g_pred[b * TT + (r - 1)] = j - 1;
    }
}

// ---------------------------------------------------------------------------
// Kernel 3: per-batch losses (bbox L1 + GIoU + weighted CE), one block/batch
// ---------------------------------------------------------------------------
__global__ void __launch_bounds__(256) loss_kernel(
    const float* __restrict__ pc, const float* __restrict__ pb,
    const int* __restrict__ tl, const float* __restrict__ tb)
{
    int b = blockIdx.x, tid = threadIdx.x;
    int lane = tid & 31, wid = tid >> 5;

    __shared__ short tc[QQ];
    __shared__ double red[8][4];

    for (int q = tid; q < QQ; q += 256) tc[q] = 13;
    __syncthreads();

    double l1sum = 0.0, gsum = 0.0;
    if (tid < TT) {
        int t = tid;
        int q = g_pred[b * TT + t];
        int lab = tl[b * TT + t];
        tc[q] = (short)lab;

        const float* pbx = pb + ((size_t)b * QQ + q) * 4;
        const float* tbx = tb + ((size_t)b * TT + t) * 4;
        float px = pbx[0], py = pbx[1], pw = pbx[2], ph = pbx[3];
        float tx = tbx[0], ty = tbx[1], tw = tbx[2], th = tbx[3];

        l1sum = (double)(fabsf(px - tx) + fabsf(py - ty) +
                         fabsf(pw - tw) + fabsf(ph - th));

        float p1x = px - 0.5f * pw, p1y = py - 0.5f * ph;
        float p2x = px + 0.5f * pw, p2y = py + 0.5f * ph;
        float t1x = tx - 0.5f * tw, t1y = ty - 0.5f * th;
        float t2x = tx + 0.5f * tw, t2y = ty + 0.5f * th;
        float a1 = (p2x - p1x) * (p2y - p1y);
        float a2 = (t2x - t1x) * (t2y - t1y);
        float ltx = fmaxf(p1x, t1x), lty = fmaxf(p1y, t1y);
        float rbx = fminf(p2x, t2x), rby = fminf(p2y, t2y);
        float iw = fmaxf(rbx - ltx, 0.f), ih = fmaxf(rby - lty, 0.f);
        float inter = iw * ih;
        float uni = a1 + a2 - inter;
        float iou = inter / uni;
        float cx1 = fminf(p1x, t1x), cy1 = fminf(p1y, t1y);
        float cx2 = fmaxf(p2x, t2x), cy2 = fmaxf(p2y, t2y);
        float ac = (cx2 - cx1) * (cy2 - cy1);
        gsum = (double)(iou - (ac - uni) / ac);
    }
    __syncthreads();

    double clsum = 0.0, wsum = 0.0;
    for (int q = tid; q < QQ; q += 256) {
        int c = tc[q];
        float w = (c == 13) ? 0.05f : 1.0f;
        float nll = g_lse[b * QQ + q] - pc[((size_t)b * QQ + q) * C1 + c];
        clsum += (double)(w * nll);
        wsum  += (double)w;
    }

    #pragma unroll
    for (int o = 16; o; o >>= 1) {
        l1sum += __shfl_down_sync(0xffffffffu, l1sum, o);
        gsum  += __shfl_down_sync(0xffffffffu, gsum, o);
        clsum += __shfl_down_sync(0xffffffffu, clsum, o);
        wsum  += __shfl_down_sync(0xffffffffu, wsum, o);
    }
    if (lane == 0) { red[wid][0] = l1sum; red[wid][1] = gsum; red[wid][2] = clsum; red[wid][3] = wsum; }
    __syncthreads();
    if (tid == 0) {
        double a = 0, g = 0, c = 0, w = 0;
        #pragma unroll
        for (int k = 0; k < 8; k++) { a += red[k][0]; g += red[k][1]; c += red[k][2]; w += red[k][3]; }
        double l1mean = a / (double)(TT * 4);
        double bbox = 5.0 * l1mean + 2.0 * (1.0 - g / (double)TT);
        double cls = c / w;
        g_partial[b] = (float)(bbox + cls);
    }
}

// ---------------------------------------------------------------------------
// Kernel 4: deterministic final sum
// ---------------------------------------------------------------------------
__global__ void finalize_kernel(float* __restrict__ out)
{
    int tid = threadIdx.x;
    __shared__ double sw[2];
    double s = (tid < BB) ? (double)g_partial[tid] : 0.0;
    #pragma unroll
    for (int o = 16; o; o >>= 1) s += __shfl_down_sync(0xffffffffu, s, o);
    if ((tid & 31) == 0) sw[tid >> 5] = s;
    __syncthreads();
    if (tid == 0) out[0] = (float)((sw[0] + sw[1]) / (double)(BB * TT));
}

// ---------------------------------------------------------------------------
extern "C" void kernel_launch(void* const* d_in, const int* in_sizes, int n_in,
                              void* d_out, int out_size)
{
    const float* pc = (const float*)d_in[0];  // predicted_class [B,Q,14]
    const float* pb = (const float*)d_in[1];  // predicted_bbox  [B,Q,4]
    const int*   tl = (const int*)d_in[2];    // target_labels   [B,T]
    const float* tb = (const float*)d_in[3];  // target_boxes    [B,T,4]

    cost_kernel<<<dim3((QQ + 255) / 256, BB), 256>>>(pc, pb, tl, tb);
    hungarian_kernel<<<BB, 256>>>();
    loss_kernel<<<BB, 256>>>(pc, pb, tl, tb);
    finalize_kernel<<<1, 64>>>((float*)d_out);
}

// round 4
// speedup vs baseline: 3.4062x; 3.4062x over previous
#include <cuda_runtime.h>
#include <math.h>
#include <float.h>

#define BB 64
#define QQ 900
#define TT 128
#define C1 14   // NUM_CLASSES+1

// Scratch (static device globals; no allocation)
__device__ float g_cost[(size_t)BB*TT*QQ];   // cost[b][t][q]
__device__ float g_lse[BB*QQ];
__device__ int   g_pred[BB*TT];              // matched query index per (b,t)
__device__ float g_partial[BB];

// ---------------------------------------------------------------------------
// Kernel 1: cost matrix + logsumexp
// ---------------------------------------------------------------------------
__global__ void __launch_bounds__(256) cost_kernel(
    const float* __restrict__ pc, const float* __restrict__ pb,
    const int* __restrict__ tl, const float* __restrict__ tb)
{
    int b = blockIdx.y;
    int tid = threadIdx.x;
    int q = blockIdx.x * 256 + tid;

    __shared__ int   slab[TT];
    __shared__ float stb[TT * 4];
    __shared__ float sprob[256 * 15];   // stride 15 -> conflict-free dynamic index

    for (int t = tid; t < TT; t += 256) {
        slab[t] = tl[b * TT + t];
        const float* tb4 = tb + ((size_t)b * TT + t) * 4;
        stb[t * 4 + 0] = tb4[0];
        stb[t * 4 + 1] = tb4[1];
        stb[t * 4 + 2] = tb4[2];
        stb[t * 4 + 3] = tb4[3];
    }

    float px = 0.f, py = 0.f, pw = 0.f, ph = 0.f;
    if (q < QQ) {
        const float* lg = pc + ((size_t)b * QQ + q) * C1;
        float l[C1];
        float m = -FLT_MAX;
        #pragma unroll
        for (int c = 0; c < C1; c++) { l[c] = lg[c]; m = fmaxf(m, l[c]); }
        float s = 0.f;
        #pragma unroll
        for (int c = 0; c < C1; c++) {
            float e = expf(l[c] - m);
            sprob[tid * 15 + c] = e;
            s += e;
        }
        float inv = -1.0f / s;   // store NEGATIVE prob (class cost is -prob)
        #pragma unroll
        for (int c = 0; c < C1; c++) sprob[tid * 15 + c] *= inv;
        g_lse[b * QQ + q] = m + logf(s);

        const float* pb4 = pb + ((size_t)b * QQ + q) * 4;
        px = pb4[0]; py = pb4[1]; pw = pb4[2]; ph = pb4[3];
    }
    __syncthreads();
    if (q >= QQ) return;

    float* out = g_cost + (size_t)b * TT * QQ + q;
    #pragma unroll 4
    for (int t = 0; t < TT; t++) {
        float tx = stb[t * 4 + 0], ty = stb[t * 4 + 1];
        float tw = stb[t * 4 + 2], th = stb[t * 4 + 3];
        float l1 = fabsf(px - tx) + fabsf(py - ty) + fabsf(pw - tw) + fabsf(ph - th);
        float cc = sprob[tid * 15 + slab[t]];
        out[(size_t)t * QQ] = cc + l1;
    }
}

// ---------------------------------------------------------------------------
// Kernel 2: exact rectangular assignment via successive shortest paths with
// JV row-reduction initialization. One block per batch.
//  phase 1: u[i] = min_j c[i][j]  (dual feasible: v=0 <= 0, c-u-v >= 0)
//  phase 2: greedy matching on tight (reduced-cost-0) argmin edges
//  phase 3: Dijkstra augment for the few remaining free rows (deferred duals)
// Produces THE optimal assignment (unique a.s. for continuous random costs),
// identical to the reference Hungarian.
// ---------------------------------------------------------------------------
__global__ void __launch_bounds__(256) hungarian_kernel()
{
    int b = blockIdx.x;
    const float* cost = g_cost + (size_t)b * TT * QQ;

    __shared__ double v[QQ + 1];
    __shared__ double spc[QQ + 1];      // absolute shortest-path costs
    __shared__ double u[TT + 1];
    __shared__ short  p[QQ + 1];        // p[j] = row assigned to col j (1-based)
    __shared__ short  way[QQ + 1];      // predecessor column in path tree
    __shared__ unsigned char used[QQ + 1];
    __shared__ short  rowargmin[TT];    // 0-based col of row minimum
    __shared__ short  freerows[TT];
    __shared__ int    s_nfree;
    __shared__ double s_minval;
    __shared__ double s_ui0;
    __shared__ int    s_j1;
    __shared__ int    s_i0;
    __shared__ int    s_done;
    __shared__ double red_v[8];
    __shared__ int    red_j[8];

    int tid = threadIdx.x;
    int lane = tid & 31, wid = tid >> 5;

    for (int j = tid; j <= QQ; j += 256) { v[j] = 0.0; p[j] = 0; }
    if (tid == 0) s_nfree = 0;
    __syncthreads();

    // ---- phase 1: row minima (+argmin, first-index tie-break) ----
    // warp w handles rows w, w+8, ... (16 rows per warp)
    for (int t = wid; t < TT; t += 8) {
        const float* crow = cost + (size_t)t * QQ;
        float bv = FLT_MAX;
        int   bj = 0x7fffffff;
        for (int j = lane; j < QQ; j += 32) {
            float c = crow[j];
            if (c < bv) { bv = c; bj = j; }
        }
        #pragma unroll
        for (int o = 16; o; o >>= 1) {
            float ov = __shfl_down_sync(0xffffffffu, bv, o);
            int   oj = __shfl_down_sync(0xffffffffu, bj, o);
            if (ov < bv || (ov == bv && oj < bj)) { bv = ov; bj = oj; }
        }
        if (lane == 0) {
            u[t + 1] = (double)bv;
            rowargmin[t] = (short)bj;
        }
    }
    __syncthreads();

    // ---- phase 2: greedy matching on tight edges (serial, deterministic) ----
    if (tid == 0) {
        int nf = 0;
        for (int t = 0; t < TT; t++) {
            int j = rowargmin[t] + 1;
            if (p[j] == 0) p[j] = (short)(t + 1);
            else freerows[nf++] = (short)(t + 1);
        }
        s_nfree = nf;
    }
    __syncthreads();
    int nfree = s_nfree;

    // ---- phase 3: Dijkstra augment for each free row ----
    for (int fi = 0; fi < nfree; fi++) {
        int i = freerows[fi];
        for (int j = tid; j <= QQ; j += 256) { spc[j] = DBL_MAX; used[j] = 0; }
        if (tid == 0) {
            p[0] = (short)i;
            spc[0] = 0.0;
            s_minval = 0.0;
            s_ui0 = u[i];
            s_i0 = i;
            s_j1 = 0;      // virtual root column
            s_done = 0;
            used[0] = 1;
        }
        __syncthreads();

        while (1) {
            int    j1prev = s_j1;
            double minVal = s_minval;
            double ui0    = s_ui0;
            int    i0     = s_i0;
            const float* crow = cost + (size_t)(i0 - 1) * QQ;

            // relax free columns via current row, track block argmin of spc
            double bv = DBL_MAX;
            int    bj = 0x7fffffff;
            for (int j = tid + 1; j <= QQ; j += 256) {
                if (!used[j] && j != j1prev) {
                    double r = minVal + (double)crow[j - 1] - ui0 - v[j];
                    double m = spc[j];
                    if (r < m) { m = r; spc[j] = r; way[j] = (short)j1prev; }
                    if (m < bv) { bv = m; bj = j; }
                }
            }
            #pragma unroll
            for (int o = 16; o; o >>= 1) {
                double ov = __shfl_down_sync(0xffffffffu, bv, o);
                int    oj = __shfl_down_sync(0xffffffffu, bj, o);
                if (ov < bv || (ov == bv && oj < bj)) { bv = ov; bj = oj; }
            }
            if (lane == 0) { red_v[wid] = bv; red_j[wid] = bj; }
            __syncthreads();
            if (wid == 0) {
                bv = (lane < 8) ? red_v[lane] : DBL_MAX;
                bj = (lane < 8) ? red_j[lane] : 0x7fffffff;
                #pragma unroll
                for (int o = 4; o; o >>= 1) {
                    double ov = __shfl_down_sync(0xffffffffu, bv, o);
                    int    oj = __shfl_down_sync(0xffffffffu, bj, o);
                    if (ov < bv || (ov == bv && oj < bj)) { bv = ov; bj = oj; }
                }
                if (lane == 0) {
                    used[j1prev] = 1;
                    int r = p[bj];
                    s_minval = bv;
                    s_j1 = bj;
                    if (r == 0) s_done = 1;
                    else { s_i0 = r; s_ui0 = u[r]; }
                }
            }
            __syncthreads();
            if (s_done) break;
        }

        double minF = s_minval;
        int sink = s_j1;

        // one-shot dual update over used columns
        for (int j = tid; j <= QQ; j += 256) {
            if (used[j]) {
                double d = minF - spc[j];
                u[p[j]] += d;
                v[j]    -= d;
            }
        }
        __syncthreads();

        // augment along alternating path
        if (tid == 0) {
            int j0 = sink;
            while (j0) {
                int jn = way[j0];
                p[j0] = p[jn];
                j0 = jn;
            }
        }
        __syncthreads();
    }

    for (int j = tid + 1; j <= QQ; j += 256) {
        int r = p[j];
        if (r > 0) g_pred[b * TT + (r - 1)] = j - 1;
    }
}

// ---------------------------------------------------------------------------
// Kernel 3: per-batch losses (bbox L1 + GIoU + weighted CE), one block/batch
// ---------------------------------------------------------------------------
__global__ void __launch_bounds__(256) loss_kernel(
    const float* __restrict__ pc, const float* __restrict__ pb,
    const int* __restrict__ tl, const float* __restrict__ tb)
{
    int b = blockIdx.x, tid = threadIdx.x;
    int lane = tid & 31, wid = tid >> 5;

    __shared__ short tc[QQ];
    __shared__ double red[8][4];

    for (int q = tid; q < QQ; q += 256) tc[q] = 13;
    __syncthreads();

    double l1sum = 0.0, gsum = 0.0;
    if (tid < TT) {
        int t = tid;
        int q = g_pred[b * TT + t];
        int lab = tl[b * TT + t];
        tc[q] = (short)lab;

        const float* pbx = pb + ((size_t)b * QQ + q) * 4;
        const float* tbx = tb + ((size_t)b * TT + t) * 4;
        float px = pbx[0], py = pbx[1], pw = pbx[2], ph = pbx[3];
        float tx = tbx[0], ty = tbx[1], tw = tbx[2], th = tbx[3];

        l1sum = (double)(fabsf(px - tx) + fabsf(py - ty) +
                         fabsf(pw - tw) + fabsf(ph - th));

        float p1x = px - 0.5f * pw, p1y = py - 0.5f * ph;
        float p2x = px + 0.5f * pw, p2y = py + 0.5f * ph;
        float t1x = tx - 0.5f * tw, t1y = ty - 0.5f * th;
        float t2x = tx + 0.5f * tw, t2y = ty + 0.5f * th;
        float a1 = (p2x - p1x) * (p2y - p1y);
        float a2 = (t2x - t1x) * (t2y - t1y);
        float ltx = fmaxf(p1x, t1x), lty = fmaxf(p1y, t1y);
        float rbx = fminf(p2x, t2x), rby = fminf(p2y, t2y);
        float iw = fmaxf(rbx - ltx, 0.f), ih = fmaxf(rby - lty, 0.f);
        float inter = iw * ih;
        float uni = a1 + a2 - inter;
        float iou = inter / uni;
        float cx1 = fminf(p1x, t1x), cy1 = fminf(p1y, t1y);
        float cx2 = fmaxf(p2x, t2x), cy2 = fmaxf(p2y, t2y);
        float ac = (cx2 - cx1) * (cy2 - cy1);
        gsum = (double)(iou - (ac - uni) / ac);
    }
    __syncthreads();

    double clsum = 0.0, wsum = 0.0;
    for (int q = tid; q < QQ; q += 256) {
        int c = tc[q];
        float w = (c == 13) ? 0.05f : 1.0f;
        float nll = g_lse[b * QQ + q] - pc[((size_t)b * QQ + q) * C1 + c];
        clsum += (double)(w * nll);
        wsum  += (double)w;
    }

    #pragma unroll
    for (int o = 16; o; o >>= 1) {
        l1sum += __shfl_down_sync(0xffffffffu, l1sum, o);
        gsum  += __shfl_down_sync(0xffffffffu, gsum, o);
        clsum += __shfl_down_sync(0xffffffffu, clsum, o);
        wsum  += __shfl_down_sync(0xffffffffu, wsum, o);
    }
    if (lane == 0) { red[wid][0] = l1sum; red[wid][1] = gsum; red[wid][2] = clsum; red[wid][3] = wsum; }
    __syncthreads();
    if (tid == 0) {
        double a = 0, g = 0, c = 0, w = 0;
        #pragma unroll
        for (int k = 0; k < 8; k++) { a += red[k][0]; g += red[k][1]; c += red[k][2]; w += red[k][3]; }
        double l1mean = a / (double)(TT * 4);
        double bbox = 5.0 * l1mean + 2.0 * (1.0 - g / (double)TT);
        double cls = c / w;
        g_partial[b] = (float)(bbox + cls);
    }
}

// ---------------------------------------------------------------------------
// Kernel 4: deterministic final sum
// ---------------------------------------------------------------------------
__global__ void finalize_kernel(float* __restrict__ out)
{
    int tid = threadIdx.x;
    __shared__ double sw[2];
    double s = (tid < BB) ? (double)g_partial[tid] : 0.0;
    #pragma unroll
    for (int o = 16; o; o >>= 1) s += __shfl_down_sync(0xffffffffu, s, o);
    if ((tid & 31) == 0) sw[tid >> 5] = s;
    __syncthreads();
    if (tid == 0) out[0] = (float)((sw[0] + sw[1]) / (double)(BB * TT));
}

// ---------------------------------------------------------------------------
extern "C" void kernel_launch(void* const* d_in, const int* in_sizes, int n_in,
                              void* d_out, int out_size)
{
    const float* pc = (const float*)d_in[0];  // predicted_class [B,Q,14]
    const float* pb = (const float*)d_in[1];  // predicted_bbox  [B,Q,4]
    const int*   tl = (const int*)d_in[2];    // target_labels   [B,T]
    const float* tb = (const float*)d_in[3];  // target_boxes    [B,T,4]

    cost_kernel<<<dim3((QQ + 255) / 256, BB), 256>>>(pc, pb, tl, tb);
    hungarian_kernel<<<BB, 256>>>();
    loss_kernel<<<BB, 256>>>(pc, pb, tl, tb);
    finalize_kernel<<<1, 64>>>((float*)d_out);
}

// round 6
// speedup vs baseline: 4.4458x; 1.3052x over previous
#include <cuda_runtime.h>
#include <math.h>
#include <float.h>

#define BB 64
#define QQ 900
#define TT 128
#define C1 14   // NUM_CLASSES+1

// Scratch (static device globals; no allocation)
__device__ float g_cost[(size_t)BB*TT*QQ];   // cost[b][t][q]
__device__ float g_lse[BB*QQ];
__device__ int   g_pred[BB*TT];              // matched query index per (b,t)
__device__ float g_partial[BB];

// ---------------------------------------------------------------------------
// Kernel 1: cost matrix + logsumexp
// ---------------------------------------------------------------------------
__global__ void __launch_bounds__(256) cost_kernel(
    const float* __restrict__ pc, const float* __restrict__ pb,
    const int* __restrict__ tl, const float* __restrict__ tb)
{
    int b = blockIdx.y;
    int tid = threadIdx.x;
    int q = blockIdx.x * 256 + tid;

    __shared__ int   slab[TT];
    __shared__ float stb[TT * 4];
    __shared__ float sprob[256 * 15];   // stride 15 -> conflict-free dynamic index

    for (int t = tid; t < TT; t += 256) {
        slab[t] = tl[b * TT + t];
        const float* tb4 = tb + ((size_t)b * TT + t) * 4;
        stb[t * 4 + 0] = tb4[0];
        stb[t * 4 + 1] = tb4[1];
        stb[t * 4 + 2] = tb4[2];
        stb[t * 4 + 3] = tb4[3];
    }

    float px = 0.f, py = 0.f, pw = 0.f, ph = 0.f;
    if (q < QQ) {
        const float* lg = pc + ((size_t)b * QQ + q) * C1;
        float l[C1];
        float m = -FLT_MAX;
        #pragma unroll
        for (int c = 0; c < C1; c++) { l[c] = lg[c]; m = fmaxf(m, l[c]); }
        float s = 0.f;
        #pragma unroll
        for (int c = 0; c < C1; c++) {
            float e = expf(l[c] - m);
            sprob[tid * 15 + c] = e;
            s += e;
        }
        float inv = -1.0f / s;   // store NEGATIVE prob (class cost is -prob)
        #pragma unroll
        for (int c = 0; c < C1; c++) sprob[tid * 15 + c] *= inv;
        g_lse[b * QQ + q] = m + logf(s);

        const float* pb4 = pb + ((size_t)b * QQ + q) * 4;
        px = pb4[0]; py = pb4[1]; pw = pb4[2]; ph = pb4[3];
    }
    __syncthreads();
    if (q >= QQ) return;

    float* out = g_cost + (size_t)b * TT * QQ + q;
    #pragma unroll 4
    for (int t = 0; t < TT; t++) {
        float tx = stb[t * 4 + 0], ty = stb[t * 4 + 1];
        float tw = stb[t * 4 + 2], th = stb[t * 4 + 3];
        float l1 = fabsf(px - tx) + fabsf(py - ty) + fabsf(pw - tw) + fabsf(ph - th);
        float cc = sprob[tid * 15 + slab[t]];
        out[(size_t)t * QQ] = cc + l1;
    }
}

// ---------------------------------------------------------------------------
// Kernel 2: exact rectangular assignment, successive shortest paths with JV
// row-reduction init. FP32 duals (selection gaps >> fp32 eps). One block/batch.
//  phase 1: u[i] = min_j c[i][j]  (parallel row argmin)
//  phase 2: greedy matching on tight argmin edges (parallel atomicMin claims)
//  phase 3: Dijkstra augment for the few remaining free rows; dual updates
//           applied only to the compact path-tree column list.
// ---------------------------------------------------------------------------
__global__ void __launch_bounds__(256) hungarian_kernel()
{
    int b = blockIdx.x;
    const float* cost = g_cost + (size_t)b * TT * QQ;

    __shared__ float v[QQ + 1];
    __shared__ float spc[QQ + 1];      // absolute shortest-path costs
    __shared__ float u[TT + 1];
    __shared__ short p[QQ + 1];        // p[j] = row assigned to col j (1-based)
    __shared__ short way[QQ + 1];      // predecessor column in path tree
    __shared__ unsigned char used[QQ + 1];
    __shared__ int   claim[QQ + 1];    // greedy claims
    __shared__ short tree[QQ + 1];     // columns committed to the path tree
    __shared__ short rowargmin[TT];    // 0-based col of row minimum
    __shared__ short freerows[TT];
    __shared__ int   s_nfree;
    __shared__ int   s_ntree;
    __shared__ float s_minval;
    __shared__ float s_ui0;
    __shared__ int   s_j1;
    __shared__ int   s_i0;
    __shared__ int   s_done;
    __shared__ float red_v[8];
    __shared__ int   red_j[8];

    int tid = threadIdx.x;
    int lane = tid & 31, wid = tid >> 5;

    for (int j = tid; j <= QQ; j += 256) { v[j] = 0.0f; p[j] = 0; claim[j] = 0x7fffffff; }
    if (tid == 0) s_nfree = 0;
    __syncthreads();

    // ---- phase 1: row minima (+argmin, first-index tie-break) ----
    for (int t = wid; t < TT; t += 8) {
        const float* crow = cost + (size_t)t * QQ;
        float bv = FLT_MAX;
        int   bj = 0x7fffffff;
        for (int j = lane; j < QQ; j += 32) {
            float c = crow[j];
            if (c < bv) { bv = c; bj = j; }
        }
        #pragma unroll
        for (int o = 16; o; o >>= 1) {
            float ov = __shfl_down_sync(0xffffffffu, bv, o);
            int   oj = __shfl_down_sync(0xffffffffu, bj, o);
            if (ov < bv || (ov == bv && oj < bj)) { bv = ov; bj = oj; }
        }
        if (lane == 0) {
            u[t + 1] = bv;
            rowargmin[t] = (short)bj;
        }
    }
    __syncthreads();

    // ---- phase 2: greedy matching (winner = lowest row index, like serial) ----
    if (tid < TT) atomicMin(&claim[rowargmin[tid] + 1], tid);
    __syncthreads();
    if (tid < TT) {
        int j = rowargmin[tid] + 1;
        if (claim[j] == tid) p[j] = (short)(tid + 1);
        else {
            int k = atomicAdd(&s_nfree, 1);
            freerows[k] = (short)(tid + 1);
        }
    }
    __syncthreads();
    int nfree = s_nfree;

    // ---- phase 3: Dijkstra augment for each free row ----
    for (int fi = 0; fi < nfree; fi++) {
        int i = freerows[fi];
        for (int j = tid; j <= QQ; j += 256) { spc[j] = FLT_MAX; used[j] = 0; }
        if (tid == 0) {
            p[0] = (short)i;
            spc[0] = 0.0f;
            s_minval = 0.0f;
            s_ui0 = u[i];
            s_i0 = i;
            s_j1 = 0;      // virtual root column
            s_done = 0;
            used[0] = 1;
            tree[0] = 0;
            s_ntree = 1;
        }
        __syncthreads();

        while (1) {
            int   j1prev = s_j1;
            float minVal = s_minval;
            float ui0    = s_ui0;
            int   i0     = s_i0;
            const float* crow = cost + (size_t)(i0 - 1) * QQ;

            // relax free columns via current row, track block argmin of spc
            float bv = FLT_MAX;
            int   bj = 0x7fffffff;
            float base = minVal - ui0;
            for (int j = tid + 1; j <= QQ; j += 256) {
                if (!used[j] && j != j1prev) {
                    float r = base + crow[j - 1] - v[j];
                    float m = spc[j];
                    if (r < m) { m = r; spc[j] = r; way[j] = (short)j1prev; }
                    if (m < bv) { bv = m; bj = j; }
                }
            }
            #pragma unroll
            for (int o = 16; o; o >>= 1) {
                float ov = __shfl_down_sync(0xffffffffu, bv, o);
                int   oj = __shfl_down_sync(0xffffffffu, bj, o);
                if (ov < bv || (ov == bv && oj < bj)) { bv = ov; bj = oj; }
            }
            if (lane == 0) { red_v[wid] = bv; red_j[wid] = bj; }
            __syncthreads();
            if (wid == 0) {
                bv = (lane < 8) ? red_v[lane] : FLT_MAX;
                bj = (lane < 8) ? red_j[lane] : 0x7fffffff;
                #pragma unroll
                for (int o = 4; o; o >>= 1) {
                    float ov = __shfl_down_sync(0xffffffffu, bv, o);
                    int   oj = __shfl_down_sync(0xffffffffu, bj, o);
                    if (ov < bv || (ov == bv && oj < bj)) { bv = ov; bj = oj; }
                }
                if (lane == 0) {
                    if (j1prev != 0) {           // root already committed
                        used[j1prev] = 1;
                        tree[s_ntree++] = (short)j1prev;
                    }
                    int r = p[bj];
                    s_minval = bv;
                    s_j1 = bj;
                    if (r == 0) s_done = 1;
                    else { s_i0 = r; s_ui0 = u[r]; }
                }
            }
            __syncthreads();
            if (s_done) break;
        }

        float minF = s_minval;
        int sink = s_j1;
        int ntree = s_ntree;

        // dual update over the compact tree only (distinct cols, distinct rows)
        for (int k = tid; k < ntree; k += 256) {
            int j = tree[k];
            float d = minF - spc[j];
            u[p[j]] += d;
            v[j]    -= d;
        }
        __syncthreads();

        // augment along alternating path
        if (tid == 0) {
            int j0 = sink;
            while (j0) {
                int jn = way[j0];
                p[j0] = p[jn];
                j0 = jn;
            }
        }
        __syncthreads();
    }

    for (int j = tid + 1; j <= QQ; j += 256) {
        int r = p[j];
        if (r > 0) g_pred[b * TT + (r - 1)] = j - 1;
    }
}

// ---------------------------------------------------------------------------
// Kernel 3: per-batch losses (bbox L1 + GIoU + weighted CE), one block/batch
// ---------------------------------------------------------------------------
__global__ void __launch_bounds__(256) loss_kernel(
    const float* __restrict__ pc, const float* __restrict__ pb,
    const int* __restrict__ tl, const float* __restrict__ tb)
{
    int b = blockIdx.x, tid = threadIdx.x;
    int lane = tid & 31, wid = tid >> 5;

    __shared__ short tc[QQ];
    __shared__ double red[8][4];

    for (int q = tid; q < QQ; q += 256) tc[q] = 13;
    __syncthreads();

    double l1sum = 0.0, gsum = 0.0;
    if (tid < TT) {
        int t = tid;
        int q = g_pred[b * TT + t];
        int lab = tl[b * TT + t];
        tc[q] = (short)lab;

        const float* pbx = pb + ((size_t)b * QQ + q) * 4;
        const float* tbx = tb + ((size_t)b * TT + t) * 4;
        float px = pbx[0], py = pbx[1], pw = pbx[2], ph = pbx[3];
        float tx = tbx[0], ty = tbx[1], tw = tbx[2], th = tbx[3];

        l1sum = (double)(fabsf(px - tx) + fabsf(py - ty) +
                         fabsf(pw - tw) + fabsf(ph - th));

        float p1x = px - 0.5f * pw, p1y = py - 0.5f * ph;
        float p2x = px + 0.5f * pw, p2y = py + 0.5f * ph;
        float t1x = tx - 0.5f * tw, t1y = ty - 0.5f * th;
        float t2x = tx + 0.5f * tw, t2y = ty + 0.5f * th;
        float a1 = (p2x - p1x) * (p2y - p1y);
        float a2 = (t2x - t1x) * (t2y - t1y);
        float ltx = fmaxf(p1x, t1x), lty = fmaxf(p1y, t1y);
        float rbx = fminf(p2x, t2x), rby = fminf(p2y, t2y);
        float iw = fmaxf(rbx - ltx, 0.f), ih = fmaxf(rby - lty, 0.f);
        float inter = iw * ih;
        float uni = a1 + a2 - inter;
        float iou = inter / uni;
        float cx1 = fminf(p1x, t1x), cy1 = fminf(p1y, t1y);
        float cx2 = fmaxf(p2x, t2x), cy2 = fmaxf(p2y, t2y);
        float ac = (cx2 - cx1) * (cy2 - cy1);
        gsum = (double)(iou - (ac - uni) / ac);
    }
    __syncthreads();

    double clsum = 0.0, wsum = 0.0;
    for (int q = tid; q < QQ; q += 256) {
        int c = tc[q];
        float w = (c == 13) ? 0.05f : 1.0f;
        float nll = g_lse[b * QQ + q] - pc[((size_t)b * QQ + q) * C1 + c];
        clsum += (double)(w * nll);
        wsum  += (double)w;
    }

    #pragma unroll
    for (int o = 16; o; o >>= 1) {
        l1sum += __shfl_down_sync(0xffffffffu, l1sum, o);
        gsum  += __shfl_down_sync(0xffffffffu, gsum, o);
        clsum += __shfl_down_sync(0xffffffffu, clsum, o);
        wsum  += __shfl_down_sync(0xffffffffu, wsum, o);
    }
    if (lane == 0) { red[wid][0] = l1sum; red[wid][1] = gsum; red[wid][2] = clsum; red[wid][3] = wsum; }
    __syncthreads();
    if (tid == 0) {
        double a = 0, g = 0, c = 0, w = 0;
        #pragma unroll
        for (int k = 0; k < 8; k++) { a += red[k][0]; g += red[k][1]; c += red[k][2]; w += red[k][3]; }
        double l1mean = a / (double)(TT * 4);
        double bbox = 5.0 * l1mean + 2.0 * (1.0 - g / (double)TT);
        double cls = c / w;
        g_partial[b] = (float)(bbox + cls);
    }
}

// ---------------------------------------------------------------------------
// Kernel 4: deterministic final sum
// ---------------------------------------------------------------------------
__global__ void finalize_kernel(float* __restrict__ out)
{
    int tid = threadIdx.x;
    __shared__ double sw[2];
    double s = (tid < BB) ? (double)g_partial[tid] : 0.0;
    #pragma unroll
    for (int o = 16; o; o >>= 1) s += __shfl_down_sync(0xffffffffu, s, o);
    if ((tid & 31) == 0) sw[tid >> 5] = s;
    __syncthreads();
    if (tid == 0) out[0] = (float)((sw[0] + sw[1]) / (double)(BB * TT));
}

// ---------------------------------------------------------------------------
extern "C" void kernel_launch(void* const* d_in, const int* in_sizes, int n_in,
                              void* d_out, int out_size)
{
    const float* pc = (const float*)d_in[0];  // predicted_class [B,Q,14]
    const float* pb = (const float*)d_in[1];  // predicted_bbox  [B,Q,4]
    const int*   tl = (const int*)d_in[2];    // target_labels   [B,T]
    const float* tb = (const float*)d_in[3];  // target_boxes    [B,T,4]

    cost_kernel<<<dim3((QQ + 255) / 256, BB), 256>>>(pc, pb, tl, tb);
    hungarian_kernel<<<BB, 256>>>();
    loss_kernel<<<BB, 256>>>(pc, pb, tl, tb);
    finalize_kernel<<<1, 64>>>((float*)d_out);
}

// round 8
// speedup vs baseline: 6.7030x; 1.5077x over previous
#include <cuda_runtime.h>
#include <math.h>
#include <float.h>

#define BB 64
#define QQ 900
#define TT 128
#define C1 14   // NUM_CLASSES+1

// Scratch (static device globals; no allocation)
__device__ __align__(16) float g_cost[(size_t)BB*TT*QQ];   // cost[b][t][q]
__device__ float g_lse[BB*QQ];
__device__ int   g_pred[BB*TT];              // matched query index per (b,t)
__device__ float g_partial[BB];

typedef unsigned long long u64;

__device__ __forceinline__ u64 pk2(float lo, float hi) {
    u64 r;
    asm("mov.b64 %0, {%1, %2};" : "=l"(r) : "f"(lo), "f"(hi));
    return r;
}
__device__ __forceinline__ u64 addx2(u64 a, u64 b) {
    u64 r;
    asm("add.rn.f32x2 %0, %1, %2;" : "=l"(r) : "l"(a), "l"(b));
    return r;
}

// ---------------------------------------------------------------------------
// Kernel 1: cost matrix + logsumexp.  Each thread owns 2 adjacent queries;
// all |pred-target| coordinate math runs as packed f32x2.
// grid: (2, B) with 256 threads: block x covers local q-window [x*512, x*512+512)
// ---------------------------------------------------------------------------
__global__ void __launch_bounds__(256) cost_kernel(
    const float* __restrict__ pc, const float* __restrict__ pb,
    const int* __restrict__ tl, const float* __restrict__ tb)
{
    int b   = blockIdx.y;
    int tid = threadIdx.x;
    int pair = blockIdx.x * 256 + tid;
    int q0   = pair * 2;
    int qloc = tid * 2;                 // local (within block window) even index
    bool active = (q0 < QQ);

    __shared__ ulonglong2 sA[TT];       // ((-tx,-tx),(-ty,-ty))
    __shared__ ulonglong2 sB[TT];       // ((-tw,-tw),(-th,-th))
    __shared__ unsigned   srow[TT];     // byte offset of probT row for label[t]
    __shared__ float      probT[C1][512];  // negative softmax probs, [class][local q]

    for (int t = tid; t < TT; t += 256) {
        const float4 tb4 = ((const float4*)tb)[b * TT + t];
        sA[t].x = pk2(-tb4.x, -tb4.x);
        sA[t].y = pk2(-tb4.y, -tb4.y);
        sB[t].x = pk2(-tb4.z, -tb4.z);
        sB[t].y = pk2(-tb4.w, -tb4.w);
        srow[t] = (unsigned)tl[b * TT + t] * (unsigned)(512 * sizeof(float));
    }

    u64 pxx = 0, pyy = 0, pww = 0, phh = 0;
    if (active) {
        #pragma unroll
        for (int k = 0; k < 2; k++) {
            int q = q0 + k;
            const float* lg = pc + ((size_t)b * QQ + q) * C1;
            float l[C1];
            float m = -FLT_MAX;
            #pragma unroll
            for (int c = 0; c < C1; c++) { l[c] = lg[c]; m = fmaxf(m, l[c]); }
            float s = 0.f;
            #pragma unroll
            for (int c = 0; c < C1; c++) { l[c] = expf(l[c] - m); s += l[c]; }
            float inv = -1.0f / s;
            #pragma unroll
            for (int c = 0; c < C1; c++) probT[c][qloc + k] = l[c] * inv;
            g_lse[b * QQ + q] = m + logf(s);
        }
        const float4 p0 = ((const float4*)pb)[b * QQ + q0];
        const float4 p1 = ((const float4*)pb)[b * QQ + q0 + 1];
        pxx = pk2(p0.x, p1.x);
        pyy = pk2(p0.y, p1.y);
        pww = pk2(p0.z, p1.z);
        phh = pk2(p0.w, p1.w);
    }
    __syncthreads();
    if (!active) return;

    const u64 MASK = 0x7FFFFFFF7FFFFFFFULL;
    u64* out = (u64*)(g_cost + (size_t)b * TT * QQ + q0);
    const char* ccbase = (const char*)&probT[0][0] + (size_t)qloc * 4;

    #pragma unroll 4
    for (int t = 0; t < TT; t++) {
        ulonglong2 A = sA[t];
        ulonglong2 Bv = sB[t];
        u64 dx = addx2(pxx, A.x)  & MASK;
        u64 dy = addx2(pyy, A.y)  & MASK;
        u64 dw = addx2(pww, Bv.x) & MASK;
        u64 dh = addx2(phh, Bv.y) & MASK;
        u64 s  = addx2(addx2(dx, dy), addx2(dw, dh));
        u64 cc = *(const u64*)(ccbase + srow[t]);
        out[(size_t)t * (QQ / 2)] = addx2(s, cc);
    }
}

// ---------------------------------------------------------------------------
// Kernel 2: exact rectangular assignment, successive shortest paths with JV
// row-reduction init. FP32 duals. One block per batch.
// ---------------------------------------------------------------------------
__global__ void __launch_bounds__(256) hungarian_kernel()
{
    int b = blockIdx.x;
    const float* cost = g_cost + (size_t)b * TT * QQ;

    __shared__ float v[QQ + 1];
    __shared__ float spc[QQ + 1];      // absolute shortest-path costs
    __shared__ float u[TT + 1];
    __shared__ short p[QQ + 1];        // p[j] = row assigned to col j (1-based)
    __shared__ short way[QQ + 1];      // predecessor column in path tree
    __shared__ unsigned char used[QQ + 1];
    __shared__ int   claim[QQ + 1];    // greedy claims
    __shared__ short tree[QQ + 1];     // columns committed to the path tree
    __shared__ short rowargmin[TT];    // 0-based col of row minimum
    __shared__ short freerows[TT];
    __shared__ int   s_nfree;
    __shared__ int   s_ntree;
    __shared__ float s_minval;
    __shared__ float s_ui0;
    __shared__ int   s_j1;
    __shared__ int   s_i0;
    __shared__ int   s_done;
    __shared__ float red_v[8];
    __shared__ int   red_j[8];

    int tid = threadIdx.x;
    int lane = tid & 31, wid = tid >> 5;

    for (int j = tid; j <= QQ; j += 256) { v[j] = 0.0f; p[j] = 0; claim[j] = 0x7fffffff; }
    if (tid == 0) s_nfree = 0;
    __syncthreads();

    // ---- phase 1: row minima (+argmin, first-index tie-break) ----
    for (int t = wid; t < TT; t += 8) {
        const float* crow = cost + (size_t)t * QQ;
        float bv = FLT_MAX;
        int   bj = 0x7fffffff;
        for (int j = lane; j < QQ; j += 32) {
            float c = crow[j];
            if (c < bv) { bv = c; bj = j; }
        }
        #pragma unroll
        for (int o = 16; o; o >>= 1) {
            float ov = __shfl_down_sync(0xffffffffu, bv, o);
            int   oj = __shfl_down_sync(0xffffffffu, bj, o);
            if (ov < bv || (ov == bv && oj < bj)) { bv = ov; bj = oj; }
        }
        if (lane == 0) {
            u[t + 1] = bv;
            rowargmin[t] = (short)bj;
        }
    }
    __syncthreads();

    // ---- phase 2: greedy matching (winner = lowest row index) ----
    if (tid < TT) atomicMin(&claim[rowargmin[tid] + 1], tid);
    __syncthreads();
    if (tid < TT) {
        int j = rowargmin[tid] + 1;
        if (claim[j] == tid) p[j] = (short)(tid + 1);
        else {
            int k = atomicAdd(&s_nfree, 1);
            freerows[k] = (short)(tid + 1);
        }
    }
    __syncthreads();
    int nfree = s_nfree;

    // ---- phase 3: Dijkstra augment for each free row ----
    for (int fi = 0; fi < nfree; fi++) {
        int i = freerows[fi];
        for (int j = tid; j <= QQ; j += 256) { spc[j] = FLT_MAX; used[j] = 0; }
        if (tid == 0) {
            p[0] = (short)i;
            spc[0] = 0.0f;
            s_minval = 0.0f;
            s_ui0 = u[i];
            s_i0 = i;
            s_j1 = 0;
            s_done = 0;
            used[0] = 1;
            tree[0] = 0;
            s_ntree = 1;
        }
        __syncthreads();

        while (1) {
            int   j1prev = s_j1;
            float minVal = s_minval;
            float ui0    = s_ui0;
            int   i0     = s_i0;
            const float* crow = cost + (size_t)(i0 - 1) * QQ;

            float bv = FLT_MAX;
            int   bj = 0x7fffffff;
            float base = minVal - ui0;
            for (int j = tid + 1; j <= QQ; j += 256) {
                if (!used[j] && j != j1prev) {
                    float r = base + crow[j - 1] - v[j];
                    float m = spc[j];
                    if (r < m) { m = r; spc[j] = r; way[j] = (short)j1prev; }
                    if (m < bv) { bv = m; bj = j; }
                }
            }
            #pragma unroll
            for (int o = 16; o; o >>= 1) {
                float ov = __shfl_down_sync(0xffffffffu, bv, o);
                int   oj = __shfl_down_sync(0xffffffffu, bj, o);
                if (ov < bv || (ov == bv && oj < bj)) { bv = ov; bj = oj; }
            }
            if (lane == 0) { red_v[wid] = bv; red_j[wid] = bj; }
            __syncthreads();
            if (wid == 0) {
                bv = (lane < 8) ? red_v[lane] : FLT_MAX;
                bj = (lane < 8) ? red_j[lane] : 0x7fffffff;
                #pragma unroll
                for (int o = 4; o; o >>= 1) {
                    float ov = __shfl_down_sync(0xffffffffu, bv, o);
                    int   oj = __shfl_down_sync(0xffffffffu, bj, o);
                    if (ov < bv || (ov == bv && oj < bj)) { bv = ov; bj = oj; }
                }
                if (lane == 0) {
                    if (j1prev != 0) {
                        used[j1prev] = 1;
                        tree[s_ntree++] = (short)j1prev;
                    }
                    int r = p[bj];
                    s_minval = bv;
                    s_j1 = bj;
                    if (r == 0) s_done = 1;
                    else { s_i0 = r; s_ui0 = u[r]; }
                }
            }
            __syncthreads();
            if (s_done) break;
        }

        float minF = s_minval;
        int sink = s_j1;
        int ntree = s_ntree;

        for (int k = tid; k < ntree; k += 256) {
            int j = tree[k];
            float d = minF - spc[j];
            u[p[j]] += d;
            v[j]    -= d;
        }
        __syncthreads();

        if (tid == 0) {
            int j0 = sink;
            while (j0) {
                int jn = way[j0];
                p[j0] = p[jn];
                j0 = jn;
            }
        }
        __syncthreads();
    }

    for (int j = tid + 1; j <= QQ; j += 256) {
        int r = p[j];
        if (r > 0) g_pred[b * TT + (r - 1)] = j - 1;
    }
}

// ---------------------------------------------------------------------------
// Kernel 3: per-batch losses (bbox L1 + GIoU + weighted CE), one block/batch
// ---------------------------------------------------------------------------
__global__ void __launch_bounds__(256) loss_kernel(
    const float* __restrict__ pc, const float* __restrict__ pb,
    const int* __restrict__ tl, const float* __restrict__ tb)
{
    int b = blockIdx.x, tid = threadIdx.x;
    int lane = tid & 31, wid = tid >> 5;

    __shared__ short tc[QQ];
    __shared__ double red[8][4];

    for (int q = tid; q < QQ; q += 256) tc[q] = 13;
    __syncthreads();

    double l1sum = 0.0, gsum = 0.0;
    if (tid < TT) {
        int t = tid;
        int q = g_pred[b * TT + t];
        int lab = tl[b * TT + t];
        tc[q] = (short)lab;

        const float* pbx = pb + ((size_t)b * QQ + q) * 4;
        const float* tbx = tb + ((size_t)b * TT + t) * 4;
        float px = pbx[0], py = pbx[1], pw = pbx[2], ph = pbx[3];
        float tx = tbx[0], ty = tbx[1], tw = tbx[2], th = tbx[3];

        l1sum = (double)(fabsf(px - tx) + fabsf(py - ty) +
                         fabsf(pw - tw) + fabsf(ph - th));

        float p1x = px - 0.5f * pw, p1y = py - 0.5f * ph;
        float p2x = px + 0.5f * pw, p2y = py + 0.5f * ph;
        float t1x = tx - 0.5f * tw, t1y = ty - 0.5f * th;
        float t2x = tx + 0.5f * tw, t2y = ty + 0.5f * th;
        float a1 = (p2x - p1x) * (p2y - p1y);
        float a2 = (t2x - t1x) * (t2y - t1y);
        float ltx = fmaxf(p1x, t1x), lty = fmaxf(p1y, t1y);
        float rbx = fminf(p2x, t2x), rby = fminf(p2y, t2y);
        float iw = fmaxf(rbx - ltx, 0.f), ih = fmaxf(rby - lty, 0.f);
        float inter = iw * ih;
        float uni = a1 + a2 - inter;
        float iou = inter / uni;
        float cx1 = fminf(p1x, t1x), cy1 = fminf(p1y, t1y);
        float cx2 = fmaxf(p2x, t2x), cy2 = fmaxf(p2y, t2y);
        float ac = (cx2 - cx1) * (cy2 - cy1);
        gsum = (double)(iou - (ac - uni) / ac);
    }
    __syncthreads();

    double clsum = 0.0, wsum = 0.0;
    for (int q = tid; q < QQ; q += 256) {
        int c = tc[q];
        float w = (c == 13) ? 0.05f : 1.0f;
        float nll = g_lse[b * QQ + q] - pc[((size_t)b * QQ + q) * C1 + c];
        clsum += (double)(w * nll);
        wsum  += (double)w;
    }

    #pragma unroll
    for (int o = 16; o; o >>= 1) {
        l1sum += __shfl_down_sync(0xffffffffu, l1sum, o);
        gsum  += __shfl_down_sync(0xffffffffu, gsum, o);
        clsum += __shfl_down_sync(0xffffffffu, clsum, o);
        wsum  += __shfl_down_sync(0xffffffffu, wsum, o);
    }
    if (lane == 0) { red[wid][0] = l1sum; red[wid][1] = gsum; red[wid][2] = clsum; red[wid][3] = wsum; }
    __syncthreads();
    if (tid == 0) {
        double a = 0, g = 0, c = 0, w = 0;
        #pragma unroll
        for (int k = 0; k < 8; k++) { a += red[k][0]; g += red[k][1]; c += red[k][2]; w += red[k][3]; }
        double l1mean = a / (double)(TT * 4);
        double bbox = 5.0 * l1mean + 2.0 * (1.0 - g / (double)TT);
        double cls = c / w;
        g_partial[b] = (float)(bbox + cls);
    }
}

// ---------------------------------------------------------------------------
// Kernel 4: deterministic final sum
// ---------------------------------------------------------------------------
__global__ void finalize_kernel(float* __restrict__ out)
{
    int tid = threadIdx.x;
    __shared__ double sw[2];
    double s = (tid < BB) ? (double)g_partial[tid] : 0.0;
    #pragma unroll
    for (int o = 16; o; o >>= 1) s += __shfl_down_sync(0xffffffffu, s, o);
    if ((tid & 31) == 0) sw[tid >> 5] = s;
    __syncthreads();
    if (tid == 0) out[0] = (float)((sw[0] + sw[1]) / (double)(BB * TT));
}

// ---------------------------------------------------------------------------
extern "C" void kernel_launch(void* const* d_in, const int* in_sizes, int n_in,
                              void* d_out, int out_size)
{
    const float* pc = (const float*)d_in[0];  // predicted_class [B,Q,14]
    const float* pb = (const float*)d_in[1];  // predicted_bbox  [B,Q,4]
    const int*   tl = (const int*)d_in[2];    // target_labels   [B,T]
    const float* tb = (const float*)d_in[3];  // target_boxes    [B,T,4]

    cost_kernel<<<dim3(2, BB), 256>>>(pc, pb, tl, tb);
    hungarian_kernel<<<BB, 256>>>();
    loss_kernel<<<BB, 256>>>(pc, pb, tl, tb);
    finalize_kernel<<<1, 64>>>((float*)d_out);
}